// round 11
// baseline (speedup 1.0000x reference)
#include <cuda_runtime.h>
#include <cuda_fp16.h>
#include <cstdint>
#include <cstddef>

#define NU   8192
#define NI   8192
#define DIN  2048
#define DH   2048
#define NTOT (NU + NI)

// ---- scratch (__device__ globals: alloc-free rule) ----
__device__ __half g_in16[(size_t)NTOT * DIN];   // 64 MB
__device__ __half g_W16[(size_t)DH * DIN];      //  8 MB
__device__ __half g_adj16[(size_t)NU * NI];     // 128 MB
__device__ __half g_adjT16[(size_t)NI * NU];    // 128 MB
__device__ __half g_supT[(size_t)DH * NTOT];    // 64 MB  support^T [h][m] row-major

// ---------------- helpers ----------------
static __device__ __forceinline__ uint32_t smem_u32(const void* p) {
    uint32_t a;
    asm("{ .reg .u64 t; cvta.to.shared.u64 t, %1; cvt.u32.u64 %0, t; }"
        : "=r"(a) : "l"(p));
    return a;
}

#define SWZ64(o) ((o) ^ (((o) >> 3) & 0x30))

#define CP_ASYNC16(dst, src) \
    asm volatile("cp.async.cg.shared.global [%0], [%1], 16;" :: "r"(dst), "l"(src) : "memory")
#define CP_COMMIT() asm volatile("cp.async.commit_group;" ::: "memory")
#define CP_WAIT4()  asm volatile("cp.async.wait_group 4;" ::: "memory")

#define LDSM_X4(r0, r1, r2, r3, addr)                                        \
    asm volatile("ldmatrix.sync.aligned.m8n8.x4.shared.b16 {%0,%1,%2,%3}, [%4];" \
        : "=r"(r0), "=r"(r1), "=r"(r2), "=r"(r3) : "r"(addr))

static __device__ __forceinline__ void mma16(float c[4], const uint32_t a[4],
                                             const uint32_t b[2]) {
    asm volatile(
        "mma.sync.aligned.m16n8k16.row.col.f32.f16.f16.f32 "
        "{%0,%1,%2,%3}, {%4,%5,%6,%7}, {%8,%9}, {%0,%1,%2,%3};"
        : "+f"(c[0]), "+f"(c[1]), "+f"(c[2]), "+f"(c[3])
        : "r"(a[0]), "r"(a[1]), "r"(a[2]), "r"(a[3]), "r"(b[0]), "r"(b[1]));
}

// ---------------- pre-pass kernels ----------------
__global__ void cvt16(const float4* __restrict__ in, uint2* __restrict__ out,
                      size_t n4) {
    size_t i = (size_t)blockIdx.x * blockDim.x + threadIdx.x;
    size_t stride = (size_t)gridDim.x * blockDim.x;
    for (; i < n4; i += stride) {
        float4 v = in[i];
        __half2 h0 = __floats2half2_rn(v.x, v.y);
        __half2 h1 = __floats2half2_rn(v.z, v.w);
        uint2 r;
        r.x = reinterpret_cast<uint32_t&>(h0);
        r.y = reinterpret_cast<uint32_t&>(h1);
        out[i] = r;
    }
}

// fused: adj(fp32) -> adj16 (row-major fp16) + adjT16 (transposed fp16)
__global__ void adjprep(const float* __restrict__ A, __half* __restrict__ A16,
                        __half* __restrict__ AT16) {
    __shared__ float t[32][33];
    int bx = blockIdx.x * 32, by = blockIdx.y * 32;
    int x = threadIdx.x, y0 = threadIdx.y;
#pragma unroll
    for (int j = 0; j < 32; j += 8) {
        float v = A[(size_t)(by + y0 + j) * NI + bx + x];
        t[y0 + j][x] = v;
        A16[(size_t)(by + y0 + j) * NI + bx + x] = __float2half(v);
    }
    __syncthreads();
#pragma unroll
    for (int j = 0; j < 32; j += 8)
        AT16[(size_t)(bx + y0 + j) * NU + by + x] = __float2half(t[x][y0 + j]);
}

// ---------------- fp16 mma.sync GEMM (software-pipelined) ----------------
// D[m][n] = sum_k A[m][k]*B[n][k]; A [M][K], B [N][K], both K-major fp16.
// EPI=0: C row-major fp16, + aux[row]  (supT build: A=W, B=input)
// EPI=1: C row-major fp32, * aux[row]  (degree scaling)
constexpr int BM = 128, BN = 128, BK = 32, STAGES = 6, GT = 256;
constexpr int STAGE_A = BM * BK * 2;            // 8 KB
constexpr int STAGE_B = BN * BK * 2;            // 8 KB
constexpr int STAGE_BYTES = STAGE_A + STAGE_B;  // 16 KB
constexpr int SMEM_T = STAGES * STAGE_BYTES;    // 96 KB

template <int EPI>
__global__ __launch_bounds__(GT, 2) void gemm16(
    const __half* __restrict__ A, const __half* __restrict__ B,
    const float* __restrict__ aux, void* __restrict__ Cv, int K, int lda,
    int ldb, int ldc) {
    extern __shared__ __align__(1024) char smem[];
    const uint32_t sbase = smem_u32(smem);
    const int tid = threadIdx.x, wid = tid >> 5, lane = tid & 31;
    const int wm = (wid >> 2) * 64, wn = (wid & 3) * 32;  // 8 warps: 2m x 4n
    const int lrow = lane & 15, lcol = lane >> 4;
    const int g = lane >> 2, t4 = lane & 3;
    const int m0 = blockIdx.y * BM, n0 = blockIdx.x * BN;

    const __half* Ab = A + (size_t)m0 * lda;
    const __half* Bb = B + (size_t)n0 * ldb;

    float acc[4][4][4];
#pragma unroll
    for (int mi = 0; mi < 4; mi++)
#pragma unroll
        for (int ni = 0; ni < 4; ni++)
#pragma unroll
            for (int i = 0; i < 4; i++) acc[mi][ni][i] = 0.f;

    uint32_t af[2][4][4];  // fragment double buffers
    uint32_t bf[2][4][2];

    // Per-warp swizzled intra-stage offsets (kb=0 base).
    // Correct kb application: with o = row*64 + lcol*16 (bit5 == 0) the kb
    // sub-block occupies exactly bit5 pre-swizzle, and the swizzle's XOR
    // source (bits 7,8) is independent of bit5, so
    //   SWZ64(o | kb<<5) == SWZ64(o) ^ (kb<<5).
    // XOR — NOT add — avoids the carry into the row field that caused the
    // R6 shared-OOB crash at stage 5 / row 127.
    uint32_t aoff[4], boff[2];
#pragma unroll
    for (int mi = 0; mi < 4; mi++)
        aoff[mi] = SWZ64((wm + mi * 16 + lrow) * 64 + lcol * 16);
#pragma unroll
    for (int p = 0; p < 2; p++)
        boff[p] = STAGE_A + SWZ64((wn + p * 16 + lrow) * 64 + lcol * 16);

    auto load_tile = [&](int kt, int st) {
        const uint32_t ab = sbase + st * STAGE_BYTES;
        const uint32_t bb = ab + STAGE_A;
        const __half* As = Ab + kt * BK;
        const __half* Bs = Bb + kt * BK;
#pragma unroll
        for (int i = 0; i < 2; i++) {
            int idx = tid + i * GT;
            int r = idx >> 2, c = idx & 3;
            CP_ASYNC16(ab + SWZ64(r * 64 + c * 16), As + (size_t)r * lda + c * 8);
        }
#pragma unroll
        for (int i = 0; i < 2; i++) {
            int idx = tid + i * GT;
            int r = idx >> 2, c = idx & 3;
            CP_ASYNC16(bb + SWZ64(r * 64 + c * 16), Bs + (size_t)r * ldb + c * 8);
        }
    };

    auto ldsm_frags = [&](int st, int kb, int buf) {
        const uint32_t base = sbase + st * STAGE_BYTES;
        const uint32_t koff = (uint32_t)(kb * 32);
#pragma unroll
        for (int mi = 0; mi < 4; mi++)
            LDSM_X4(af[buf][mi][0], af[buf][mi][1], af[buf][mi][2],
                    af[buf][mi][3], base + (aoff[mi] ^ koff));
#pragma unroll
        for (int p = 0; p < 2; p++) {
            uint32_t r0, r1, r2, r3;
            LDSM_X4(r0, r1, r2, r3, base + (boff[p] ^ koff));
            bf[buf][2 * p][0] = r0;
            bf[buf][2 * p + 1][0] = r1;
            bf[buf][2 * p][1] = r2;
            bf[buf][2 * p + 1][1] = r3;
        }
    };

    auto domma = [&](int buf) {
#pragma unroll
        for (int mi = 0; mi < 4; mi++)
#pragma unroll
            for (int ni = 0; ni < 4; ni++)
                mma16(acc[mi][ni], af[buf][mi], bf[buf][ni]);
    };

    const int kiters = K / BK;
    // prologue: stage tiles 0..4
#pragma unroll
    for (int t = 0; t < STAGES - 1; t++) {
        load_tile(t, t);
        CP_COMMIT();
    }
    CP_WAIT4();
    __syncthreads();
    ldsm_frags(0, 0, 0);

    int st = 0, lst = STAGES - 1;
    for (int kt = 0; kt < kiters; kt++) {
        // kb = 0: prefetch kb=1 frags, issue next tile's loads, mma buf0
        ldsm_frags(st, 1, 1);
        if (kt + STAGES - 1 < kiters) load_tile(kt + STAGES - 1, lst);
        CP_COMMIT();
        if (++lst == STAGES) lst = 0;
        domma(0);
        // kb = 1: advance stage, prefetch next stage kb=0, mma buf1
        if (kt + 1 < kiters) {
            CP_WAIT4();
            __syncthreads();
            if (++st == STAGES) st = 0;
            ldsm_frags(st, 0, 0);
        }
        domma(1);
    }

    // ---- epilogue: row-major C, aux indexed by row ----
    if (EPI == 1) {
        float* C = (float*)Cv;
#pragma unroll
        for (int mi = 0; mi < 4; mi++) {
            const int r0 = wm + mi * 16 + g;
            const float d0 = aux[m0 + r0];
            const float d1 = aux[m0 + r0 + 8];
            float* p0 = C + (size_t)(m0 + r0) * ldc + n0;
            float* p1 = C + (size_t)(m0 + r0 + 8) * ldc + n0;
#pragma unroll
            for (int ni = 0; ni < 4; ni++) {
                const int c0 = wn + ni * 8 + 2 * t4;
                float2 v0 = {d0 * acc[mi][ni][0], d0 * acc[mi][ni][1]};
                float2 v1 = {d1 * acc[mi][ni][2], d1 * acc[mi][ni][3]};
                *reinterpret_cast<float2*>(p0 + c0) = v0;
                *reinterpret_cast<float2*>(p1 + c0) = v1;
            }
        }
    } else {
        __half* C = (__half*)Cv;
#pragma unroll
        for (int mi = 0; mi < 4; mi++) {
            const int r0 = wm + mi * 16 + g;
            const float b0 = aux[m0 + r0];
            const float b1 = aux[m0 + r0 + 8];
            __half* p0 = C + (size_t)(m0 + r0) * ldc + n0;
            __half* p1 = C + (size_t)(m0 + r0 + 8) * ldc + n0;
#pragma unroll
            for (int ni = 0; ni < 4; ni++) {
                const int c0 = wn + ni * 8 + 2 * t4;
                __half2 v0 = __floats2half2_rn(acc[mi][ni][0] + b0,
                                               acc[mi][ni][1] + b0);
                __half2 v1 = __floats2half2_rn(acc[mi][ni][2] + b1,
                                               acc[mi][ni][3] + b1);
                *reinterpret_cast<__half2*>(p0 + c0) = v0;
                *reinterpret_cast<__half2*>(p1 + c0) = v1;
            }
        }
    }
}

// ---------------- launch ----------------
extern "C" void kernel_launch(void* const* d_in, const int* in_sizes, int n_in,
                              void* d_out, int out_size) {
    const float* input = (const float*)d_in[0];   // (16384, 2048)
    const float* adj = (const float*)d_in[1];     // (8192, 8192)
    const float* degree = (const float*)d_in[2];  // (16384,)
    const float* W = (const float*)d_in[3];       // (2048, 2048)
    const float* b = (const float*)d_in[4];       // (2048,)
    float* out = (float*)d_out;                   // (16384, 2048)

    __half *in16, *W16, *adj16, *adjT16, *supT;
    cudaGetSymbolAddress((void**)&in16, g_in16);
    cudaGetSymbolAddress((void**)&W16, g_W16);
    cudaGetSymbolAddress((void**)&adj16, g_adj16);
    cudaGetSymbolAddress((void**)&adjT16, g_adjT16);
    cudaGetSymbolAddress((void**)&supT, g_supT);

    cudaFuncSetAttribute(gemm16<0>, cudaFuncAttributeMaxDynamicSharedMemorySize,
                         SMEM_T);
    cudaFuncSetAttribute(gemm16<1>, cudaFuncAttributeMaxDynamicSharedMemorySize,
                         SMEM_T);

    // pre-passes
    cvt16<<<4096, 256>>>((const float4*)input, (uint2*)in16,
                         (size_t)NTOT * DIN / 4);
    cvt16<<<2048, 256>>>((const float4*)W, (uint2*)W16, (size_t)DH * DIN / 4);
    adjprep<<<dim3(NI / 32, NU / 32), dim3(32, 8)>>>(adj, adj16, adjT16);

    // GEMM1 (transpose-free): supT[h][m] = fp16( sum_k W[h][k]*in[m][k] + b[h] )
    gemm16<0><<<dim3(NTOT / BN, DH / BM), GT, SMEM_T>>>(
        W16, in16, b, supT, DIN, DIN, DIN, NTOT);

    // GEMM2: out_u[m][n] = deg[m] * sum_i adj[m][i] * supT[n][NU+i]
    gemm16<1><<<dim3(DH / BN, NU / BM), GT, SMEM_T>>>(
        adj16, supT + NU, degree, out, NI, NI, NTOT, DH);

    // GEMM3: out_i[m][n] = deg[NU+m] * sum_u adjT[m][u] * supT[n][u]
    gemm16<1><<<dim3(DH / BN, NI / BM), GT, SMEM_T>>>(
        adjT16, supT, degree + NU, out + (size_t)NU * DH, NU, NU, NTOT, DH);
}

// round 12
// speedup vs baseline: 1.0462x; 1.0462x over previous
#include <cuda_runtime.h>
#include <cuda_fp16.h>
#include <cstdint>
#include <cstddef>

#define NU   8192
#define NI   8192
#define DIN  2048
#define DH   2048
#define NTOT (NU + NI)

// ---- scratch (__device__ globals: alloc-free rule) ----
__device__ __half g_in16[(size_t)NTOT * DIN];   // 64 MB
__device__ __half g_W16[(size_t)DH * DIN];      //  8 MB
__device__ __half g_adj16[(size_t)NU * NI];     // 128 MB
__device__ __half g_adjT16[(size_t)NI * NU];    // 128 MB
__device__ __half g_supT[(size_t)DH * NTOT];    // 64 MB  support^T [h][m] row-major

// ---------------- helpers ----------------
static __device__ __forceinline__ uint32_t smem_u32(const void* p) {
    uint32_t a;
    asm("{ .reg .u64 t; cvta.to.shared.u64 t, %1; cvt.u32.u64 %0, t; }"
        : "=r"(a) : "l"(p));
    return a;
}

#define SWZ64(o) ((o) ^ (((o) >> 3) & 0x30))

#define CP_ASYNC16(dst, src) \
    asm volatile("cp.async.cg.shared.global [%0], [%1], 16;" :: "r"(dst), "l"(src) : "memory")
#define CP_COMMIT() asm volatile("cp.async.commit_group;" ::: "memory")
#define CP_WAIT3()  asm volatile("cp.async.wait_group 3;" ::: "memory")

#define LDSM_X4(r0, r1, r2, r3, addr)                                        \
    asm volatile("ldmatrix.sync.aligned.m8n8.x4.shared.b16 {%0,%1,%2,%3}, [%4];" \
        : "=r"(r0), "=r"(r1), "=r"(r2), "=r"(r3) : "r"(addr))

static __device__ __forceinline__ void mma16(float c[4], const uint32_t a[4],
                                             const uint32_t b[2]) {
    asm volatile(
        "mma.sync.aligned.m16n8k16.row.col.f32.f16.f16.f32 "
        "{%0,%1,%2,%3}, {%4,%5,%6,%7}, {%8,%9}, {%0,%1,%2,%3};"
        : "+f"(c[0]), "+f"(c[1]), "+f"(c[2]), "+f"(c[3])
        : "r"(a[0]), "r"(a[1]), "r"(a[2]), "r"(a[3]), "r"(b[0]), "r"(b[1]));
}

// ---------------- pre-pass kernels ----------------
__global__ void cvt16(const float4* __restrict__ in, uint2* __restrict__ out,
                      size_t n4) {
    size_t i = (size_t)blockIdx.x * blockDim.x + threadIdx.x;
    size_t stride = (size_t)gridDim.x * blockDim.x;
    for (; i < n4; i += stride) {
        float4 v = in[i];
        __half2 h0 = __floats2half2_rn(v.x, v.y);
        __half2 h1 = __floats2half2_rn(v.z, v.w);
        uint2 r;
        r.x = reinterpret_cast<uint32_t&>(h0);
        r.y = reinterpret_cast<uint32_t&>(h1);
        out[i] = r;
    }
}

// fused: adj(fp32) -> adj16 (row-major fp16) + adjT16 (transposed fp16)
__global__ void adjprep(const float* __restrict__ A, __half* __restrict__ A16,
                        __half* __restrict__ AT16) {
    __shared__ float t[32][33];
    int bx = blockIdx.x * 32, by = blockIdx.y * 32;
    int x = threadIdx.x, y0 = threadIdx.y;
#pragma unroll
    for (int j = 0; j < 32; j += 8) {
        float v = A[(size_t)(by + y0 + j) * NI + bx + x];
        t[y0 + j][x] = v;
        A16[(size_t)(by + y0 + j) * NI + bx + x] = __float2half(v);
    }
    __syncthreads();
#pragma unroll
    for (int j = 0; j < 32; j += 8)
        AT16[(size_t)(bx + y0 + j) * NU + by + x] = __float2half(t[x][y0 + j]);
}

// ---------------- fp16 mma.sync GEMM (fat warp tiles, 1 CTA/SM) ----------------
// D[m][n] = sum_k A[m][k]*B[n][k]; A [M][K], B [N][K], both K-major fp16.
// CTA 256x128x32, 8 warps as 4m x 2n, warp tile 64x64 (acc 128 regs).
// EPI=0: C row-major fp16, + aux[row]  (supT build: A=W, B=input)
// EPI=1: C row-major fp32, * aux[row]  (degree scaling)
constexpr int BM = 256, BN = 128, BK = 32, STAGES = 5, GT = 256;
constexpr int STAGE_A = BM * BK * 2;            // 16 KB
constexpr int STAGE_B = BN * BK * 2;            //  8 KB
constexpr int STAGE_BYTES = STAGE_A + STAGE_B;  // 24 KB
constexpr int SMEM_T = STAGES * STAGE_BYTES;    // 120 KB

template <int EPI>
__global__ __launch_bounds__(GT, 1) void gemm16(
    const __half* __restrict__ A, const __half* __restrict__ B,
    const float* __restrict__ aux, void* __restrict__ Cv, int K, int lda,
    int ldb, int ldc) {
    extern __shared__ __align__(1024) char smem[];
    const uint32_t sbase = smem_u32(smem);
    const int tid = threadIdx.x, wid = tid >> 5, lane = tid & 31;
    const int wm = (wid >> 1) * 64, wn = (wid & 1) * 64;  // 8 warps: 4m x 2n
    const int lrow = lane & 15, lcol = lane >> 4;
    const int g = lane >> 2, t4 = lane & 3;
    const int m0 = blockIdx.y * BM, n0 = blockIdx.x * BN;

    const __half* Ab = A + (size_t)m0 * lda;
    const __half* Bb = B + (size_t)n0 * ldb;

    float acc[4][8][4];
#pragma unroll
    for (int mi = 0; mi < 4; mi++)
#pragma unroll
        for (int ni = 0; ni < 8; ni++)
#pragma unroll
            for (int i = 0; i < 4; i++) acc[mi][ni][i] = 0.f;

    uint32_t af[2][4][4];  // fragment double buffers
    uint32_t bf[2][8][2];

    // Per-warp swizzled intra-stage offsets (kb=0 base). kb applied by XOR of
    // kb<<5 (bit 5 of the pre-swizzle offset is always 0 and the swizzle's
    // XOR source bits 7,8 are independent of bit 5), avoiding row-carry.
    uint32_t aoff[4], boff[4];
#pragma unroll
    for (int mi = 0; mi < 4; mi++)
        aoff[mi] = SWZ64((wm + mi * 16 + lrow) * 64 + lcol * 16);
#pragma unroll
    for (int p = 0; p < 4; p++)
        boff[p] = STAGE_A + SWZ64((wn + p * 16 + lrow) * 64 + lcol * 16);

    auto load_tile = [&](int kt, int st) {
        const uint32_t ab = sbase + st * STAGE_BYTES;
        const uint32_t bb = ab + STAGE_A;
        const __half* As = Ab + kt * BK;
        const __half* Bs = Bb + kt * BK;
#pragma unroll
        for (int i = 0; i < 4; i++) {  // A: 256 rows x 64B = 1024 chunks
            int idx = tid + i * GT;
            int r = idx >> 2, c = idx & 3;
            CP_ASYNC16(ab + SWZ64(r * 64 + c * 16), As + (size_t)r * lda + c * 8);
        }
#pragma unroll
        for (int i = 0; i < 2; i++) {  // B: 128 rows x 64B = 512 chunks
            int idx = tid + i * GT;
            int r = idx >> 2, c = idx & 3;
            CP_ASYNC16(bb + SWZ64(r * 64 + c * 16), Bs + (size_t)r * ldb + c * 8);
        }
    };

    auto ldsm_frags = [&](int st, int kb, int buf) {
        const uint32_t base = sbase + st * STAGE_BYTES;
        const uint32_t koff = (uint32_t)(kb * 32);
#pragma unroll
        for (int mi = 0; mi < 4; mi++)
            LDSM_X4(af[buf][mi][0], af[buf][mi][1], af[buf][mi][2],
                    af[buf][mi][3], base + (aoff[mi] ^ koff));
#pragma unroll
        for (int p = 0; p < 4; p++) {
            uint32_t r0, r1, r2, r3;
            LDSM_X4(r0, r1, r2, r3, base + (boff[p] ^ koff));
            bf[buf][2 * p][0] = r0;
            bf[buf][2 * p + 1][0] = r1;
            bf[buf][2 * p][1] = r2;
            bf[buf][2 * p + 1][1] = r3;
        }
    };

    auto domma = [&](int buf) {
#pragma unroll
        for (int mi = 0; mi < 4; mi++)
#pragma unroll
            for (int ni = 0; ni < 8; ni++)
                mma16(acc[mi][ni], af[buf][mi], bf[buf][ni]);
    };

    const int kiters = K / BK;
    // prologue: stage tiles 0..3
#pragma unroll
    for (int t = 0; t < STAGES - 1; t++) {
        load_tile(t, t);
        CP_COMMIT();
    }
    CP_WAIT3();
    __syncthreads();
    ldsm_frags(0, 0, 0);

    int st = 0, lst = STAGES - 1;
    for (int kt = 0; kt < kiters; kt++) {
        // kb = 0: prefetch kb=1 frags, issue next tile's loads, mma buf0
        ldsm_frags(st, 1, 1);
        if (kt + STAGES - 1 < kiters) load_tile(kt + STAGES - 1, lst);
        CP_COMMIT();
        if (++lst == STAGES) lst = 0;
        domma(0);
        // kb = 1: advance stage, prefetch next stage kb=0, mma buf1
        if (kt + 1 < kiters) {
            CP_WAIT3();
            __syncthreads();
            if (++st == STAGES) st = 0;
            ldsm_frags(st, 0, 0);
        }
        domma(1);
    }

    // ---- epilogue: row-major C, aux indexed by row ----
    if (EPI == 1) {
        float* C = (float*)Cv;
#pragma unroll
        for (int mi = 0; mi < 4; mi++) {
            const int r0 = wm + mi * 16 + g;
            const float d0 = aux[m0 + r0];
            const float d1 = aux[m0 + r0 + 8];
            float* p0 = C + (size_t)(m0 + r0) * ldc + n0;
            float* p1 = C + (size_t)(m0 + r0 + 8) * ldc + n0;
#pragma unroll
            for (int ni = 0; ni < 8; ni++) {
                const int c0 = wn + ni * 8 + 2 * t4;
                float2 v0 = {d0 * acc[mi][ni][0], d0 * acc[mi][ni][1]};
                float2 v1 = {d1 * acc[mi][ni][2], d1 * acc[mi][ni][3]};
                *reinterpret_cast<float2*>(p0 + c0) = v0;
                *reinterpret_cast<float2*>(p1 + c0) = v1;
            }
        }
    } else {
        __half* C = (__half*)Cv;
#pragma unroll
        for (int mi = 0; mi < 4; mi++) {
            const int r0 = wm + mi * 16 + g;
            const float b0 = aux[m0 + r0];
            const float b1 = aux[m0 + r0 + 8];
            __half* p0 = C + (size_t)(m0 + r0) * ldc + n0;
            __half* p1 = C + (size_t)(m0 + r0 + 8) * ldc + n0;
#pragma unroll
            for (int ni = 0; ni < 8; ni++) {
                const int c0 = wn + ni * 8 + 2 * t4;
                __half2 v0 = __floats2half2_rn(acc[mi][ni][0] + b0,
                                               acc[mi][ni][1] + b0);
                __half2 v1 = __floats2half2_rn(acc[mi][ni][2] + b1,
                                               acc[mi][ni][3] + b1);
                *reinterpret_cast<__half2*>(p0 + c0) = v0;
                *reinterpret_cast<__half2*>(p1 + c0) = v1;
            }
        }
    }
}

// ---------------- launch ----------------
extern "C" void kernel_launch(void* const* d_in, const int* in_sizes, int n_in,
                              void* d_out, int out_size) {
    const float* input = (const float*)d_in[0];   // (16384, 2048)
    const float* adj = (const float*)d_in[1];     // (8192, 8192)
    const float* degree = (const float*)d_in[2];  // (16384,)
    const float* W = (const float*)d_in[3];       // (2048, 2048)
    const float* b = (const float*)d_in[4];       // (2048,)
    float* out = (float*)d_out;                   // (16384, 2048)

    __half *in16, *W16, *adj16, *adjT16, *supT;
    cudaGetSymbolAddress((void**)&in16, g_in16);
    cudaGetSymbolAddress((void**)&W16, g_W16);
    cudaGetSymbolAddress((void**)&adj16, g_adj16);
    cudaGetSymbolAddress((void**)&adjT16, g_adjT16);
    cudaGetSymbolAddress((void**)&supT, g_supT);

    cudaFuncSetAttribute(gemm16<0>, cudaFuncAttributeMaxDynamicSharedMemorySize,
                         SMEM_T);
    cudaFuncSetAttribute(gemm16<1>, cudaFuncAttributeMaxDynamicSharedMemorySize,
                         SMEM_T);

    // pre-passes
    cvt16<<<4096, 256>>>((const float4*)input, (uint2*)in16,
                         (size_t)NTOT * DIN / 4);
    cvt16<<<2048, 256>>>((const float4*)W, (uint2*)W16, (size_t)DH * DIN / 4);
    adjprep<<<dim3(NI / 32, NU / 32), dim3(32, 8)>>>(adj, adj16, adjT16);

    // GEMM1 (transpose-free): supT[h][m] = fp16( sum_k W[h][k]*in[m][k] + b[h] )
    gemm16<0><<<dim3(NTOT / BN, DH / BM), GT, SMEM_T>>>(
        W16, in16, b, supT, DIN, DIN, DIN, NTOT);

    // GEMM2: out_u[m][n] = deg[m] * sum_i adj[m][i] * supT[n][NU+i]
    gemm16<1><<<dim3(DH / BN, NU / BM), GT, SMEM_T>>>(
        adj16, supT + NU, degree, out, NI, NI, NTOT, DH);

    // GEMM3: out_i[m][n] = deg[NU+m] * sum_u adjT[m][u] * supT[n][u]
    gemm16<1><<<dim3(DH / BN, NI / BM), GT, SMEM_T>>>(
        adjT16, supT, degree + NU, out + (size_t)NU * DH, NU, NU, NTOT, DH);
}